// round 17
// baseline (speedup 1.0000x reference)
#include <cuda_runtime.h>
#include <cuda_fp16.h>
#include <cstdint>

// ---------------------------------------------------------------------------
// Problem constants
// ---------------------------------------------------------------------------
#define ROWS_TOTAL 50176        // 256*14*14
#define KDIM       384
#define NDIM       1536
#define M_TILE     128
#define N_TILE     128
#define NUM_KF     (KDIM / 16)        // 24 k-fragments
#define LN_EPS     1e-6f

// Fragment-packed operands (no cudaMalloc -> __device__ globals).
// A: [mfrag 0..3135][kf 0..23][lane 0..31] -> uint4 {a0,a1,a2,a3}  (38.5MB)
// B: [npair 0..95][kf 0..23][lane 0..31]  -> uint4 {b0,b1,b0',b1'} (1.18MB)
__device__ uint4 g_xf[(ROWS_TOTAL / 16) * NUM_KF * 32];
__device__ uint4 g_wf[(NDIM / 16) * NUM_KF * 32];

// ---------------------------------------------------------------------------
// Inline PTX
// ---------------------------------------------------------------------------
#define MMA_U4(c, a4, b0v, b1v) \
    asm volatile("mma.sync.aligned.m16n8k16.row.col.f32.f16.f16.f32 " \
                 "{%0,%1,%2,%3}, {%4,%5,%6,%7}, {%8,%9}, {%0,%1,%2,%3};" \
                 : "+f"((c)[0]), "+f"((c)[1]), "+f"((c)[2]), "+f"((c)[3]) \
                 : "r"((a4).x), "r"((a4).y), "r"((a4).z), "r"((a4).w), \
                   "r"(b0v), "r"(b1v))

// Fast GELU: v * sigmoid(1.59577(v + 0.044715 v^3)) — branch-free, 2 MUFU.
__device__ __forceinline__ float gelu_fast(float v) {
    float t = v * v;
    float z = 1.5957691216f * v * fmaf(0.044715f, t, 1.0f);
    float e = __expf(-z);
    return __fdividef(v, 1.0f + e);
}

__device__ __forceinline__ uint32_t pack2(float a, float b) {
    return (uint32_t)__half_as_ushort(__float2half_rn(a))
         | ((uint32_t)__half_as_ushort(__float2half_rn(b)) << 16);
}

// ---------------------------------------------------------------------------
// Kernel 1: fused prepass (512-thread blocks).
//  Blocks [0, LN_BLOCKS): LayerNorm 16 rows -> one A m-fragment row of g_xf.
//  Blocks [LN_BLOCKS, +WF_BLOCKS): W fp32 -> B-fragment pack (g_wf).
// ---------------------------------------------------------------------------
#define LN_BLOCKS  (ROWS_TOTAL / 16)           // 3136
#define WF_WORDS   ((NDIM / 16) * NUM_KF * 32) // 73728
#define WF_BLOCKS  (WF_WORDS / 512)            // 144
#define SROW       200                         // smem row stride in words

__global__ __launch_bounds__(512) void prepass_kernel(
    const float* __restrict__ x,
    const float* __restrict__ gamma,
    const float* __restrict__ beta,
    const float* __restrict__ W)
{
    if (blockIdx.x >= LN_BLOCKS) {
        // ---- W fragment pack ----
        int id   = (blockIdx.x - LN_BLOCKS) * 512 + threadIdx.x;  // 0..73727
        int lane = id & 31;
        int t    = id >> 5;
        int kf   = t % NUM_KF;
        int np   = t / NUM_KF;          // 0..95
        int nA   = np * 16 + (lane >> 2);
        int nB   = nA + 8;
        int k    = kf * 16 + (lane & 3) * 2;
        const float* wA = W + (size_t)nA * KDIM + k;
        const float* wB = W + (size_t)nB * KDIM + k;
        uint4 v;
        v.x = pack2(wA[0], wA[1]);
        v.y = pack2(wA[8], wA[9]);
        v.z = pack2(wB[0], wB[1]);
        v.w = pack2(wB[8], wB[9]);
        g_wf[id] = v;
        return;
    }

    // ---- LayerNorm: 16 warps, one row each; stage fp16 rows in smem ----
    __shared__ uint32_t sx[16 * SROW];
    const int wid  = threadIdx.x >> 5;
    const int lane = threadIdx.x & 31;
    const int row  = blockIdx.x * 16 + wid;
    const float4* xr = reinterpret_cast<const float4*>(x + (size_t)row * KDIM);

    float4 v[3];
    float s = 0.f, ss = 0.f;
#pragma unroll
    for (int i = 0; i < 3; i++) {
        v[i] = xr[lane + i * 32];
        s  += v[i].x + v[i].y + v[i].z + v[i].w;
        ss += v[i].x * v[i].x + v[i].y * v[i].y + v[i].z * v[i].z + v[i].w * v[i].w;
    }
#pragma unroll
    for (int o = 16; o > 0; o >>= 1) {
        s  += __shfl_xor_sync(0xffffffffu, s, o);
        ss += __shfl_xor_sync(0xffffffffu, ss, o);
    }
    float mu  = s * (1.0f / KDIM);
    float var = ss * (1.0f / KDIM) - mu * mu;
    float rs  = rsqrtf(var + LN_EPS);

#pragma unroll
    for (int i = 0; i < 3; i++) {
        int col = (lane + i * 32) * 4;
        float4 gv = *reinterpret_cast<const float4*>(gamma + col);
        float4 bv = *reinterpret_cast<const float4*>(beta + col);
        float n0 = fmaf(v[i].x - mu, rs * gv.x, bv.x);
        float n1 = fmaf(v[i].y - mu, rs * gv.y, bv.y);
        float n2 = fmaf(v[i].z - mu, rs * gv.z, bv.z);
        float n3 = fmaf(v[i].w - mu, rs * gv.w, bv.w);
        sx[wid * SROW + (lane + i * 32) * 2]     = pack2(n0, n1);
        sx[wid * SROW + (lane + i * 32) * 2 + 1] = pack2(n2, n3);
    }
    __syncthreads();

    // ---- A fragment pack: this block = m-fragment row blockIdx.x ----
#pragma unroll
    for (int idx = threadIdx.x; idx < NUM_KF * 32; idx += 512) {
        int kf = idx >> 5;
        int l  = idx & 31;
        int r  = l >> 2;
        int w0 = kf * 8 + (l & 3);   // word offset of (k,k+1) within row
        uint4 o;
        o.x = sx[r * SROW + w0];
        o.y = sx[(r + 8) * SROW + w0];
        o.z = sx[r * SROW + w0 + 4];
        o.w = sx[(r + 8) * SROW + w0 + 4];
        g_xf[((size_t)blockIdx.x * NUM_KF + kf) * 32 + l] = o;
    }
}

// ---------------------------------------------------------------------------
// Kernel 2: fp16 GEMM + bias + fast GELU — zero smem, zero barriers.
// CTA tile 128x128; 8 warps (4M x 2N), warp tile 32x64.
// Asymmetric prefetch: A fragments triple-buffered (distance 2, covers L2-hit
// latency ~234cyc); B fragments double-buffered (distance 1, L1-hot).
// Fully unrolled kf loop (indices compile-time).
// ---------------------------------------------------------------------------
__global__ __launch_bounds__(256, 2) void gemm_kernel(
    const float* __restrict__ bias,
    float* __restrict__ out)
{
    const int tid    = threadIdx.x;
    const int wid    = tid >> 5;
    const int lane   = tid & 31;
    const int warp_m = wid & 3;          // 0..3 (32-row quarters)
    const int warp_n = wid >> 2;         // 0..1 (64-col halves)

    const int n0 = blockIdx.x * N_TILE;  // n fastest -> A-fragment L2 reuse
    const int m0 = blockIdx.y * M_TILE;

    const uint4* pA = g_xf + ((size_t)(m0 / 16) + warp_m * 2) * (NUM_KF * 32) + lane;
    const uint4* pB = g_wf + ((size_t)(n0 / 16) + warp_n * 4) * (NUM_KF * 32) + lane;

#define LDA(af, kf)                                          \
    do {                                                     \
        (af)[0] = __ldg(pA + (0 * NUM_KF + (kf)) * 32);      \
        (af)[1] = __ldg(pA + (1 * NUM_KF + (kf)) * 32);      \
    } while (0)

#define LDB(bf, kf)                                          \
    do {                                                     \
        (bf)[0] = __ldg(pB + (0 * NUM_KF + (kf)) * 32);      \
        (bf)[1] = __ldg(pB + (1 * NUM_KF + (kf)) * 32);      \
        (bf)[2] = __ldg(pB + (2 * NUM_KF + (kf)) * 32);      \
        (bf)[3] = __ldg(pB + (3 * NUM_KF + (kf)) * 32);      \
    } while (0)

#define MMAS(af, bf)                                                        \
    do {                                                                    \
        _Pragma("unroll")                                                   \
        for (int mf = 0; mf < 2; mf++) {                                    \
            _Pragma("unroll")                                               \
            for (int p = 0; p < 4; p++) {                                   \
                MMA_U4(acc[mf][p * 2],     (af)[mf], (bf)[p].x, (bf)[p].y); \
                MMA_U4(acc[mf][p * 2 + 1], (af)[mf], (bf)[p].z, (bf)[p].w); \
            }                                                               \
        }                                                                   \
    } while (0)

    float acc[2][8][4];
#pragma unroll
    for (int a = 0; a < 2; a++)
#pragma unroll
        for (int b = 0; b < 8; b++)
#pragma unroll
            for (int c = 0; c < 4; c++) acc[a][b][c] = 0.f;

    uint4 af[3][2];   // A: 3-deep rotation, distance 2
    uint4 bf[2][4];   // B: 2-deep rotation, distance 1

    // prologue
    LDA(af[0], 0);
    LDB(bf[0], 0);
    LDA(af[1], 1);

#pragma unroll
    for (int kf = 0; kf < NUM_KF; kf++) {
        if (kf + 2 < NUM_KF) LDA(af[(kf + 2) % 3], kf + 2);
        if (kf + 1 < NUM_KF) LDB(bf[(kf + 1) % 2], kf + 1);
        MMAS(af[kf % 3], bf[kf % 2]);
    }

    // epilogue: bias + fast GELU, direct float2 stores (sectors fully covered)
    const int tg = lane & 3, gp = lane >> 2;
#pragma unroll
    for (int mf = 0; mf < 2; mf++) {
#pragma unroll
        for (int nf = 0; nf < 8; nf++) {
            int row = m0 + warp_m * 32 + mf * 16 + gp;
            int col = n0 + warp_n * 64 + nf * 8 + tg * 2;
            float2 bv = *reinterpret_cast<const float2*>(bias + col);
            float2 o0, o1;
            o0.x = gelu_fast(acc[mf][nf][0] + bv.x);
            o0.y = gelu_fast(acc[mf][nf][1] + bv.y);
            o1.x = gelu_fast(acc[mf][nf][2] + bv.x);
            o1.y = gelu_fast(acc[mf][nf][3] + bv.y);
            *reinterpret_cast<float2*>(out + (size_t)row * NDIM + col) = o0;
            *reinterpret_cast<float2*>(out + (size_t)(row + 8) * NDIM + col) = o1;
        }
    }
#undef LDA
#undef LDB
#undef MMAS
}

// ---------------------------------------------------------------------------
// Launch
// ---------------------------------------------------------------------------
extern "C" void kernel_launch(void* const* d_in, const int* in_sizes, int n_in,
                              void* d_out, int out_size) {
    const float* x     = (const float*)d_in[0];
    const float* gamma = (const float*)d_in[1];
    const float* beta  = (const float*)d_in[2];
    const float* W     = (const float*)d_in[3];
    const float* b     = (const float*)d_in[4];
    float* out = (float*)d_out;

    prepass_kernel<<<LN_BLOCKS + WF_BLOCKS, 512>>>(x, gamma, beta, W);

    dim3 grid(NDIM / N_TILE, ROWS_TOTAL / M_TILE);   // (12, 392)
    gemm_kernel<<<grid, 256>>>(b, out);
}